// round 17
// baseline (speedup 1.0000x reference)
#include <cuda_runtime.h>
#include <cuda_bf16.h>
#include <cuda_fp16.h>
#include <stdint.h>

#define BB 4
#define CC 64
#define WDIM 64
#define NN 4096
#define MQ 128
#define KTILE 32
#define NSPLIT 4
#define TILES_PER_SPLIT (NN/KTILE/NSPLIT)   // 32
#define L2E 1.44269504088896f
#define PBLK 32

#define QSTRIDE 80
#define KSTRIDE 80
#define VSTRIDE 144
// triple-buffered K/V (single fp16 V)
#define SM_Q   0                 // 128 x 80 = 10240
#define SM_K   10240             // 3 x 2560
#define KBUF   2560
#define SM_VH  17920             // 3 x 4608
#define VBUF   4608
#define SMEM_TOTAL 31744

// ---- global scratch ----
__device__ __align__(16) __nv_bfloat16 g_Q16[BB*NN*32];
__device__ __align__(16) __nv_bfloat16 g_K16[BB*NN*32];
__device__ __align__(16) __half g_V16[BB*NN*CC];
__device__ __align__(16) float g_Opart[NSPLIT][BB][NN][CC];   // 16MB partials
__device__ float g_Spart[NSPLIT][BB][NN];
__device__ float g_Mpart[NSPLIT][BB][NN];

// ---- helpers ----
__device__ __forceinline__ uint32_t s2u(const void* p) {
    uint32_t a;
    asm("{ .reg .u64 t; cvta.to.shared.u64 t, %1; cvt.u32.u64 %0, t; }" : "=r"(a) : "l"(p));
    return a;
}
__device__ __forceinline__ float ex2f(float x) {
    float r; asm("ex2.approx.f32 %0, %1;" : "=f"(r) : "f"(x)); return r;
}
// packs: lower 16 bits = lo arg, upper 16 = hi arg
__device__ __forceinline__ uint32_t cvt2bf(float hi, float lo) {
    uint32_t r; asm("cvt.rn.bf16x2.f32 %0, %1, %2;" : "=r"(r) : "f"(hi), "f"(lo)); return r;
}
__device__ __forceinline__ uint32_t cvt2h(float hi, float lo) {
    __half2 h = __floats2half2_rn(lo, hi);      // .x = lo -> lower 16 bits
    return *(uint32_t*)&h;
}
__device__ __forceinline__ void cpa16(uint32_t dst, const void* src) {
    asm volatile("cp.async.cg.shared.global [%0], [%1], 16;" :: "r"(dst), "l"(src));
}
__device__ __forceinline__ void ldsm4(uint32_t* r, uint32_t a) {
    asm volatile("ldmatrix.sync.aligned.m8n8.x4.shared.b16 {%0,%1,%2,%3}, [%4];"
        : "=r"(r[0]), "=r"(r[1]), "=r"(r[2]), "=r"(r[3]) : "r"(a));
}
__device__ __forceinline__ void ldsm4t(uint32_t* r, uint32_t a) {
    asm volatile("ldmatrix.sync.aligned.m8n8.x4.trans.shared.b16 {%0,%1,%2,%3}, [%4];"
        : "=r"(r[0]), "=r"(r[1]), "=r"(r[2]), "=r"(r[3]) : "r"(a));
}
__device__ __forceinline__ void mma16816(float* d, const uint32_t* a, const uint32_t* b) {
    asm volatile(
        "mma.sync.aligned.m16n8k16.row.col.f32.bf16.bf16.f32 "
        "{%0,%1,%2,%3}, {%4,%5,%6,%7}, {%8,%9}, {%0,%1,%2,%3};"
        : "+f"(d[0]), "+f"(d[1]), "+f"(d[2]), "+f"(d[3])
        : "r"(a[0]), "r"(a[1]), "r"(a[2]), "r"(a[3]), "r"(b[0]), "r"(b[1]));
}
__device__ __forceinline__ void mma16816h(float* d, const uint32_t* a, const uint32_t* b) {
    asm volatile(
        "mma.sync.aligned.m16n8k16.row.col.f32.f16.f16.f32 "
        "{%0,%1,%2,%3}, {%4,%5,%6,%7}, {%8,%9}, {%0,%1,%2,%3};"
        : "+f"(d[0]), "+f"(d[1]), "+f"(d[2]), "+f"(d[3])
        : "r"(a[0]), "r"(a[1]), "r"(a[2]), "r"(a[3]), "r"(b[0]), "r"(b[1]));
}

// ---------------------------------------------------------------------------
// Prep (R14-identical): 1x1 convs -> packed bf16 Q/K + fp16 V.
// 512 blocks x 320 threads: 32 pixels x 10 warp-groups.
// ---------------------------------------------------------------------------
__global__ __launch_bounds__(320) void prep_kernel(
    const float* __restrict__ x,
    const float* __restrict__ Wq, const float* __restrict__ bq,
    const float* __restrict__ Wk, const float* __restrict__ bk,
    const float* __restrict__ Wv, const float* __restrict__ bv)
{
    __shared__ float xs[CC][PBLK];     // 8KB
    __shared__ float wv_s[CC][CC];     // 16KB
    __shared__ float wq_s[8][CC];
    __shared__ float wk_s[8][CC];
    __shared__ float bv_s[CC];
    __shared__ float bq_s[8], bk_s[8];

    const int b  = blockIdx.x >> 7;
    const int n0 = (blockIdx.x & 127) * PBLK;
    const int t  = threadIdx.x;

    for (int i = t; i < CC*PBLK; i += 320)
        xs[i >> 5][i & 31] = x[(b*CC + (i >> 5))*NN + n0 + (i & 31)];
    for (int i = t; i < CC*CC; i += 320) wv_s[i >> 6][i & 63] = Wv[i];
    for (int i = t; i < 8*CC;  i += 320) { wq_s[i >> 6][i & 63] = Wq[i]; wk_s[i >> 6][i & 63] = Wk[i]; }
    if (t < CC) bv_s[t] = bv[t];
    if (t < 8)  { bq_s[t] = bq[t]; bk_s[t] = bk[t]; }
    __syncthreads();

    const int g = t >> 5;        // warp id 0..9
    const int p = t & 31;
    const int n = n0 + p;

    if (g == 0) {
        float acc[8];
        #pragma unroll
        for (int d = 0; d < 8; d++) acc[d] = 0.f;
        for (int c = 0; c < CC; c++) {
            float xc = xs[c][p];
            #pragma unroll
            for (int d = 0; d < 8; d++) acc[d] = fmaf(wq_s[d][c], xc, acc[d]);
        }
        float qv[8];
        #pragma unroll
        for (int d = 0; d < 8; d++) qv[d] = acc[d] + bq_s[d];

        uint32_t u[16];
        float lo[8];
        #pragma unroll
        for (int i = 0; i < 4; i++) {
            uint32_t hh = cvt2bf(qv[2*i+1], qv[2*i]);
            u[i] = hh;
            lo[2*i]   = qv[2*i]   - __uint_as_float(hh << 16);
            lo[2*i+1] = qv[2*i+1] - __uint_as_float(hh & 0xFFFF0000u);
        }
        u[4] = u[0];
        u[5] = u[0]; u[6] = u[1]; u[7] = u[2]; u[8] = u[3];
        #pragma unroll
        for (int i = 0; i < 4; i++) u[9+i] = cvt2bf(lo[2*i+1], lo[2*i]);
        u[13] = u[9];
        u[14] = 0; u[15] = 0;
        uint4* dst = (uint4*)&g_Q16[(size_t)(b*NN + n)*32];
        dst[0] = make_uint4(u[0],u[1],u[2],u[3]);
        dst[1] = make_uint4(u[4],u[5],u[6],u[7]);
        dst[2] = make_uint4(u[8],u[9],u[10],u[11]);
        dst[3] = make_uint4(u[12],u[13],u[14],u[15]);
    } else if (g == 1) {
        float acc[8];
        #pragma unroll
        for (int d = 0; d < 8; d++) acc[d] = 0.f;
        for (int c = 0; c < CC; c++) {
            float xc = xs[c][p];
            #pragma unroll
            for (int d = 0; d < 8; d++) acc[d] = fmaf(wk_s[d][c], xc, acc[d]);
        }
        float kv[8];
        #pragma unroll
        for (int d = 0; d < 8; d++) kv[d] = acc[d] + bk_s[d];

        uint32_t u[16];
        float lo[8];
        #pragma unroll
        for (int i = 0; i < 4; i++) {
            uint32_t hh = cvt2bf(kv[2*i+1], kv[2*i]);
            u[i] = hh;
            lo[2*i]   = kv[2*i]   - __uint_as_float(hh << 16);
            lo[2*i+1] = kv[2*i+1] - __uint_as_float(hh & 0xFFFF0000u);
        }
        float colc = (float)(n % WDIM) - 31.5f;   // exact in bf16
        float rowc = (float)(n / WDIM) - 31.5f;
        u[4] = cvt2bf(rowc, colc);
        #pragma unroll
        for (int i = 0; i < 4; i++) u[5+i] = cvt2bf(lo[2*i+1], lo[2*i]);
        u[9] = u[0]; u[10] = u[1]; u[11] = u[2]; u[12] = u[3];
        u[13] = u[4];
        u[14] = 0; u[15] = 0;
        uint4* dst = (uint4*)&g_K16[(size_t)(b*NN + n)*32];
        dst[0] = make_uint4(u[0],u[1],u[2],u[3]);
        dst[1] = make_uint4(u[4],u[5],u[6],u[7]);
        dst[2] = make_uint4(u[8],u[9],u[10],u[11]);
        dst[3] = make_uint4(u[12],u[13],u[14],u[15]);
    } else {
        const int e0 = (g - 2) * 8;
        float acc[8];
        #pragma unroll
        for (int e = 0; e < 8; e++) acc[e] = 0.f;
        for (int c = 0; c < CC; c++) {
            float xc = xs[c][p];
            #pragma unroll
            for (int e = 0; e < 8; e++) acc[e] = fmaf(wv_s[e0 + e][c], xc, acc[e]);
        }
        const size_t gbase = (size_t)(b*NN + n)*CC + e0;
        #pragma unroll
        for (int e = 0; e < 8; e++)
            g_V16[gbase + e] = __float2half(acc[e] + bv_s[e0 + e]);
    }
}

// ---------------------------------------------------------------------------
// Split-K mma.sync flash attention: 512 CTAs (4 splits x 4 b x 32 qtiles),
// 128 threads; each warp owns TWO 16-row query blocks (32 rows) so K and V
// fragments are loaded once per tile and reused -> crossbar traffic per MMA
// halves. Scores: packed 32-dim bf16. Softmax: running max + rescale.
// PV: single-term fp16. 4-way split merge with max exchange.
// Triple-buffered K/V, one __syncthreads per tile.
// ---------------------------------------------------------------------------
#define STAGE(tile, bbuf) do {                                              \
    int m0s = (tile)*KTILE;                                                 \
    { int row = t >> 2, seg = t & 3;                                        \
      cpa16(sb + SM_K + (bbuf)*KBUF + row*KSTRIDE + seg*16,                 \
            &g_K16[(size_t)(b*NN + m0s + row)*32 + seg*8]); }               \
    _Pragma("unroll")                                                       \
    for (int j5 = 0; j5 < 2; j5++) {                                        \
        int id = t + 128*j5; int row = id >> 3, seg = id & 7;               \
        cpa16(sb + SM_VH + (bbuf)*VBUF + row*VSTRIDE + seg*16,              \
              &g_V16[(size_t)(b*NN + m0s + row)*CC + seg*8]);               \
    }                                                                       \
} while (0)

__global__ __launch_bounds__(128, 4) void attn_kernel()
{
    extern __shared__ char smem[];
    const uint32_t sb = s2u(smem);
    const int t = threadIdx.x;
    const int w = t >> 5;
    const int l = t & 31;
    const int sp = blockIdx.x >> 7;
    const int b  = (blockIdx.x >> 5) & 3;
    const int n0 = (blockIdx.x & 31) * MQ;
    const int qr0 = w * 32;
    const int t0 = sp * TILES_PER_SPLIT;

    // stage Q (plain loads): 128 rows x 64B
    #pragma unroll
    for (int j = 0; j < 4; j++) {
        int id = t + 128*j;
        int row = id >> 2, seg = id & 3;
        uint4 v = *(const uint4*)&g_Q16[(size_t)(b*NN + n0 + row)*32 + seg*8];
        *(uint4*)(smem + SM_Q + row*QSTRIDE + seg*16) = v;
    }

    // prefetch first tile of this split into buffer 0
    STAGE(t0, 0);
    asm volatile("cp.async.commit_group;" ::: "memory");

    __syncthreads();   // Q staged

    uint32_t qA0[4], qB0[4], qA1[4], qB1[4];
    {
        uint32_t qa = sb + SM_Q + (qr0 + (l & 7) + ((l >> 3) & 1)*8)*QSTRIDE + (l >> 4)*16;
        ldsm4(qA0, qa);
        ldsm4(qB0, qa + 32);
        ldsm4(qA1, qa + 16*QSTRIDE);
        ldsm4(qB1, qa + 16*QSTRIDE + 32);
    }

    float OA[8][4], OB[8][4];
    #pragma unroll
    for (int j = 0; j < 8; j++) {
        OA[j][0]=0.f; OA[j][1]=0.f; OA[j][2]=0.f; OA[j][3]=0.f;
        OB[j][0]=0.f; OB[j][1]=0.f; OB[j][2]=0.f; OB[j][3]=0.f;
    }
    float sA0 = 0.f, sB0 = 0.f, sA1 = 0.f, sB1 = 0.f;
    float MA0 = -1e30f, MB0 = -1e30f, MA1 = -1e30f, MB1 = -1e30f;

    int cb = 0, nb = 1;   // current / next buffer (mod 3)
    for (int ti = 0; ti < TILES_PER_SPLIT; ti++) {
        if (ti + 1 < TILES_PER_SPLIT) STAGE(t0 + ti + 1, nb);
        asm volatile("cp.async.commit_group;" ::: "memory");
        asm volatile("cp.async.wait_group 1;" ::: "memory");
        __syncthreads();   // single barrier per tile (triple buffer makes WAR safe)

        // ---- scores for both row blocks; K frags loaded once ----
        const uint32_t kbase = sb + SM_K + cb*KBUF;
        float SA[4][4], SB[4][4];
        #pragma unroll
        for (int p2 = 0; p2 < 2; p2++) {
            uint32_t ka = kbase + (p2*16 + (l & 7) + (l >> 4)*8)*KSTRIDE + ((l >> 3) & 1)*16;
            uint32_t kA[4], kB[4];
            ldsm4(kA, ka);
            ldsm4(kB, ka + 32);
            float* a0 = SA[2*p2]; float* a1 = SA[2*p2+1];
            float* b0 = SB[2*p2]; float* b1 = SB[2*p2+1];
            a0[0]=0.f;a0[1]=0.f;a0[2]=0.f;a0[3]=0.f;
            a1[0]=0.f;a1[1]=0.f;a1[2]=0.f;a1[3]=0.f;
            b0[0]=0.f;b0[1]=0.f;b0[2]=0.f;b0[3]=0.f;
            b1[0]=0.f;b1[1]=0.f;b1[2]=0.f;b1[3]=0.f;
            mma16816(a0, qA0, kA);     mma16816(a0, qB0, kB);
            mma16816(a1, qA0, kA + 2); mma16816(a1, qB0, kB + 2);
            mma16816(b0, qA1, kA);     mma16816(b0, qB1, kB);
            mma16816(b1, qA1, kA + 2); mma16816(b1, qB1, kB + 2);
        }

        // ---- per-row tile max ----
        float rmA0 = fmaxf(fmaxf(SA[0][0], SA[0][1]), fmaxf(SA[1][0], SA[1][1]));
        rmA0 = fmaxf(rmA0, fmaxf(fmaxf(SA[2][0], SA[2][1]), fmaxf(SA[3][0], SA[3][1])));
        float rmB0 = fmaxf(fmaxf(SA[0][2], SA[0][3]), fmaxf(SA[1][2], SA[1][3]));
        rmB0 = fmaxf(rmB0, fmaxf(fmaxf(SA[2][2], SA[2][3]), fmaxf(SA[3][2], SA[3][3])));
        float rmA1 = fmaxf(fmaxf(SB[0][0], SB[0][1]), fmaxf(SB[1][0], SB[1][1]));
        rmA1 = fmaxf(rmA1, fmaxf(fmaxf(SB[2][0], SB[2][1]), fmaxf(SB[3][0], SB[3][1])));
        float rmB1 = fmaxf(fmaxf(SB[0][2], SB[0][3]), fmaxf(SB[1][2], SB[1][3]));
        rmB1 = fmaxf(rmB1, fmaxf(fmaxf(SB[2][2], SB[2][3]), fmaxf(SB[3][2], SB[3][3])));
        rmA0 = fmaxf(rmA0, __shfl_xor_sync(0xffffffffu, rmA0, 1));
        rmA0 = fmaxf(rmA0, __shfl_xor_sync(0xffffffffu, rmA0, 2));
        rmB0 = fmaxf(rmB0, __shfl_xor_sync(0xffffffffu, rmB0, 1));
        rmB0 = fmaxf(rmB0, __shfl_xor_sync(0xffffffffu, rmB0, 2));
        rmA1 = fmaxf(rmA1, __shfl_xor_sync(0xffffffffu, rmA1, 1));
        rmA1 = fmaxf(rmA1, __shfl_xor_sync(0xffffffffu, rmA1, 2));
        rmB1 = fmaxf(rmB1, __shfl_xor_sync(0xffffffffu, rmB1, 1));
        rmB1 = fmaxf(rmB1, __shfl_xor_sync(0xffffffffu, rmB1, 2));

        float nA0 = fmaxf(MA0, rmA0), nB0 = fmaxf(MB0, rmB0);
        float nA1 = fmaxf(MA1, rmA1), nB1 = fmaxf(MB1, rmB1);
        float aA0 = ex2f((MA0 - nA0) * L2E), aB0 = ex2f((MB0 - nB0) * L2E);
        float aA1 = ex2f((MA1 - nA1) * L2E), aB1 = ex2f((MB1 - nB1) * L2E);
        MA0 = nA0; MB0 = nB0; MA1 = nA1; MB1 = nB1;
        const float cA0 = nA0 * L2E, cB0 = nB0 * L2E;
        const float cA1 = nA1 * L2E, cB1 = nB1 * L2E;
        sA0 *= aA0; sB0 *= aB0; sA1 *= aA1; sB1 *= aB1;
        #pragma unroll
        for (int j = 0; j < 8; j++) {
            OA[j][0] *= aA0; OA[j][1] *= aA0; OA[j][2] *= aB0; OA[j][3] *= aB0;
            OB[j][0] *= aA1; OB[j][1] *= aA1; OB[j][2] *= aB1; OB[j][3] *= aB1;
        }

        // ---- exp ----
        #pragma unroll
        for (int j = 0; j < 4; j++) {
            SA[j][0] = ex2f(fmaf(SA[j][0], L2E, -cA0));
            SA[j][1] = ex2f(fmaf(SA[j][1], L2E, -cA0));
            SA[j][2] = ex2f(fmaf(SA[j][2], L2E, -cB0));
            SA[j][3] = ex2f(fmaf(SA[j][3], L2E, -cB0));
            sA0 += SA[j][0] + SA[j][1];
            sB0 += SA[j][2] + SA[j][3];
            SB[j][0] = ex2f(fmaf(SB[j][0], L2E, -cA1));
            SB[j][1] = ex2f(fmaf(SB[j][1], L2E, -cA1));
            SB[j][2] = ex2f(fmaf(SB[j][2], L2E, -cB1));
            SB[j][3] = ex2f(fmaf(SB[j][3], L2E, -cB1));
            sA1 += SB[j][0] + SB[j][1];
            sB1 += SB[j][2] + SB[j][3];
        }

        // ---- PV: V frags loaded once, used by both row blocks ----
        const uint32_t vhb = sb + SM_VH + cb*VBUF;
        #pragma unroll
        for (int kt = 0; kt < 2; kt++) {
            const float* sa = SA[2*kt];
            const float* sc = SA[2*kt+1];
            const float* sb2 = SB[2*kt];
            const float* sd = SB[2*kt+1];
            uint32_t phA[4], phB[4];
            phA[0] = cvt2h(sa[1], sa[0]);
            phA[1] = cvt2h(sa[3], sa[2]);
            phA[2] = cvt2h(sc[1], sc[0]);
            phA[3] = cvt2h(sc[3], sc[2]);
            phB[0] = cvt2h(sb2[1], sb2[0]);
            phB[1] = cvt2h(sb2[3], sb2[2]);
            phB[2] = cvt2h(sd[1], sd[0]);
            phB[3] = cvt2h(sd[3], sd[2]);
            uint32_t rowoff = (kt*16 + (l & 7) + ((l >> 3) & 1)*8)*VSTRIDE + (l >> 4)*16;
            #pragma unroll
            for (int cp = 0; cp < 4; cp++) {
                uint32_t vh[4];
                ldsm4t(vh, vhb + rowoff + cp*32);
                mma16816h(OA[2*cp],     phA, vh);
                mma16816h(OA[2*cp + 1], phA, vh + 2);
                mma16816h(OB[2*cp],     phB, vh);
                mma16816h(OB[2*cp + 1], phB, vh + 2);
            }
        }

        cb = nb;
        nb = (nb == 2) ? 0 : nb + 1;
    }

    // ---- epilogue: write UNNORMALIZED partials + per-row (sum, max) ----
    sA0 += __shfl_xor_sync(0xffffffffu, sA0, 1);
    sA0 += __shfl_xor_sync(0xffffffffu, sA0, 2);
    sB0 += __shfl_xor_sync(0xffffffffu, sB0, 1);
    sB0 += __shfl_xor_sync(0xffffffffu, sB0, 2);
    sA1 += __shfl_xor_sync(0xffffffffu, sA1, 1);
    sA1 += __shfl_xor_sync(0xffffffffu, sA1, 2);
    sB1 += __shfl_xor_sync(0xffffffffu, sB1, 1);
    sB1 += __shfl_xor_sync(0xffffffffu, sB1, 2);

    const int nR = n0 + qr0 + (l >> 2);
    if ((l & 3) == 0) {
        g_Spart[sp][b][nR]      = sA0;
        g_Spart[sp][b][nR + 8]  = sB0;
        g_Spart[sp][b][nR + 16] = sA1;
        g_Spart[sp][b][nR + 24] = sB1;
        g_Mpart[sp][b][nR]      = MA0;
        g_Mpart[sp][b][nR + 8]  = MB0;
        g_Mpart[sp][b][nR + 16] = MA1;
        g_Mpart[sp][b][nR + 24] = MB1;
    }
    #pragma unroll
    for (int j = 0; j < 8; j++) {
        int ch = j*8 + (l & 3)*2;
        *(float2*)&g_Opart[sp][b][nR][ch]      = make_float2(OA[j][0], OA[j][1]);
        *(float2*)&g_Opart[sp][b][nR + 8][ch]  = make_float2(OA[j][2], OA[j][3]);
        *(float2*)&g_Opart[sp][b][nR + 16][ch] = make_float2(OB[j][0], OB[j][1]);
        *(float2*)&g_Opart[sp][b][nR + 24][ch] = make_float2(OB[j][2], OB[j][3]);
    }
}

// ---------------------------------------------------------------------------
// Reduce with 4-way max exchange:
//   Mg = max_sp M_sp; w_sp = 2^((M_sp-Mg)*L2E)
//   out[b][c][n] = (sum_sp O_sp*w_sp)[n][c] / (sum_sp S_sp*w_sp)[n]
// 256 blocks x 256 threads, coalesced via 64x64 smem transpose.
// ---------------------------------------------------------------------------
__global__ __launch_bounds__(256) void reduce_kernel(float* __restrict__ out)
{
    __shared__ float tile[CC][65];
    __shared__ float w_s[NSPLIT][64];
    __shared__ float inv_s[64];
    const int b  = blockIdx.x >> 6;
    const int n0 = (blockIdx.x & 63) * 64;
    const int t  = threadIdx.x;

    if (t < 64) {
        float M[NSPLIT], S[NSPLIT];
        float Mg = -1e30f;
        #pragma unroll
        for (int s = 0; s < NSPLIT; s++) {
            M[s] = g_Mpart[s][b][n0 + t];
            S[s] = g_Spart[s][b][n0 + t];
            Mg = fmaxf(Mg, M[s]);
        }
        float den = 0.f;
        #pragma unroll
        for (int s = 0; s < NSPLIT; s++) {
            float ws = ex2f((M[s] - Mg) * L2E);
            w_s[s][t] = ws;
            den = fmaf(S[s], ws, den);
        }
        inv_s[t] = 1.0f / den;
    }
    __syncthreads();

    #pragma unroll
    for (int j = 0; j < 4; j++) {
        int idx = t + 256*j;
        int r = idx >> 4, c4 = (idx & 15)*4;
        float iv = inv_s[r];
        float v0 = 0.f, v1 = 0.f, v2 = 0.f, v3 = 0.f;
        #pragma unroll
        for (int s = 0; s < NSPLIT; s++) {
            float4 a = *(const float4*)&g_Opart[s][b][n0 + r][c4];
            float ws = w_s[s][r];
            v0 = fmaf(a.x, ws, v0);
            v1 = fmaf(a.y, ws, v1);
            v2 = fmaf(a.z, ws, v2);
            v3 = fmaf(a.w, ws, v3);
        }
        tile[c4    ][r] = v0 * iv;
        tile[c4 + 1][r] = v1 * iv;
        tile[c4 + 2][r] = v2 * iv;
        tile[c4 + 3][r] = v3 * iv;
    }
    __syncthreads();

    #pragma unroll
    for (int j = 0; j < 4; j++) {
        int idx = t + 256*j;
        int c = idx >> 4, nn = (idx & 15)*4;
        // scalar LDS (row stride 65 floats not 16B-aligned); vector STG
        float4 vv = make_float4(tile[c][nn], tile[c][nn + 1],
                                tile[c][nn + 2], tile[c][nn + 3]);
        *(float4*)&out[(size_t)(b*CC + c)*NN + n0 + nn] = vv;
    }
}

extern "C" void kernel_launch(void* const* d_in, const int* in_sizes, int n_in,
                              void* d_out, int out_size)
{
    const float* x  = (const float*)d_in[0];
    const float* Wq = (const float*)d_in[1];
    const float* bq = (const float*)d_in[2];
    const float* Wk = (const float*)d_in[3];
    const float* bk = (const float*)d_in[4];
    const float* Wv = (const float*)d_in[5];
    const float* bv = (const float*)d_in[6];
    float* out = (float*)d_out;

    prep_kernel<<<BB*(NN/PBLK), 320>>>(x, Wq, bq, Wk, bk, Wv, bv);
    attn_kernel<<<NSPLIT*BB*(NN/MQ), 128, SMEM_TOTAL>>>();
    reduce_kernel<<<BB*(NN/64), 256>>>(out);
}